// round 6
// baseline (speedup 1.0000x reference)
#include <cuda_runtime.h>
#include <cstdint>

#define NBLOCKS   128
#define NTHREADS  256
#define BB        64
#define HH        1024
#define II        256
#define SS        512
#define OO        256
#define KTOT      1280        // 1024 (h) + 256 (x)
#define NPER      8           // output neurons per CTA (1024/128)
#define PSTRIDE   260         // panel row stride in floats (pad: conflict-free LDS.128)
#define PANEL_FLOATS (64 * PSTRIDE)

// ---- grid barrier state (persists across graph replays; generation-relative) ----
__device__ unsigned g_bar_count = 0;
__device__ unsigned g_bar_gen   = 0;

__device__ __forceinline__ void grid_barrier(unsigned base_gen, unsigned step) {
    __syncthreads();
    if (threadIdx.x == 0) {
        __threadfence();
        unsigned prev = atomicAdd(&g_bar_count, 1u);
        if (prev == NBLOCKS - 1) {
            g_bar_count = 0;          // reset before releasing
            __threadfence();
            atomicAdd(&g_bar_gen, 1u);
        } else {
            while (*(volatile unsigned*)&g_bar_gen - base_gen < step) { }
        }
        __threadfence();
    }
    __syncthreads();
}

// ---- cp.async helpers ----
__device__ __forceinline__ void cp_async16(uint32_t dst, const void* src) {
    asm volatile("cp.async.cg.shared.global [%0], [%1], 16;" :: "r"(dst), "l"(src));
}
__device__ __forceinline__ void cp_commit() {
    asm volatile("cp.async.commit_group;" ::: "memory");
}
template <int N>
__device__ __forceinline__ void cp_wait() {
    asm volatile("cp.async.wait_group %0;" :: "n"(N) : "memory");
}

// Stage one 64x256-float panel (rows = b) into smem with PSTRIDE padding.
__device__ __forceinline__ void stage_panel(const float* __restrict__ srcBase,
                                            int srcRowStride, uint32_t dstU32) {
#pragma unroll
    for (int i = 0; i < 16; ++i) {
        int idx = threadIdx.x + i * NTHREADS;   // 0..4095 float4 slots
        int row = idx >> 6;                     // 0..63  (b)
        int c4  = idx & 63;                     // float4 column
        cp_async16(dstU32 + (uint32_t)(row * PSTRIDE + c4 * 4) * 4u,
                   srcBase + (size_t)row * srcRowStride + c4 * 4);
    }
    cp_commit();
}

// Compute one 256-k panel contribution for this thread's (b, b+32) x 8n tile.
__device__ __forceinline__ void compute_panel(const float* __restrict__ panel,
                                              const float* __restrict__ wbase, // w_s + p*256
                                              int bp, int q,
                                              float acc0[8], float acc1[8]) {
    const float* h0p = panel + bp * PSTRIDE + q * 32;
    const float* h1p = h0p + 32 * PSTRIDE;
    const float* wq  = wbase + q * 32;
#pragma unroll
    for (int it = 0; it < 8; ++it) {
        float4 ha = *(const float4*)(h0p + it * 4);
        float4 hb = *(const float4*)(h1p + it * 4);
#pragma unroll
        for (int n = 0; n < 8; ++n) {
            float4 w = *(const float4*)(wq + n * KTOT + it * 4);
            acc0[n] = fmaf(ha.x, w.x, fmaf(ha.y, w.y, fmaf(ha.z, w.z, fmaf(ha.w, w.w, acc0[n]))));
            acc1[n] = fmaf(hb.x, w.x, fmaf(hb.y, w.y, fmaf(hb.z, w.z, fmaf(hb.w, w.w, acc1[n]))));
        }
    }
}

// smem layout (floats):
//   w_s    : 8*1280            = 10240
//   bias_s : 16
//   panel0 : 64*260            = 16640
//   panel1 : 64*260            = 16640
//   red    : 8*512             =  4096
static constexpr int SMEM_FLOATS = 10240 + 16 + 2 * PANEL_FLOATS + 4096;
static constexpr int SMEM_BYTES  = SMEM_FLOATS * 4;   // 190,528 B

__global__ void __launch_bounds__(NTHREADS, 1)
rnn_persistent_kernel(const float* __restrict__ x,
                      const float* __restrict__ wih,
                      const float* __restrict__ whh,
                      const float* __restrict__ bias,
                      float* __restrict__ hstates)   // [S+1][B][H] region of d_out
{
    extern __shared__ float smem[];
    float* w_s    = smem;                         // [8][1280]
    float* bias_s = smem + NPER * KTOT;           // [16]
    float* panelA = bias_s + 16;
    float* panelB = panelA + PANEL_FLOATS;
    float* red    = panelB + PANEL_FLOATS;        // [8 q][512 (b*8+n)]

    const int tid = threadIdx.x;
    const int n0  = blockIdx.x * NPER;
    const int bp  = tid & 31;                     // b and b+32
    const int q   = tid >> 5;                     // k-chunk / warp id (0..7)

    // Preload combined weight rows: k<1024 -> W_hh, else W_ih.
    for (int i = tid; i < NPER * KTOT; i += NTHREADS) {
        int n = i / KTOT;
        int k = i - n * KTOT;
        w_s[i] = (k < HH) ? whh[(size_t)(n0 + n) * HH + k]
                          : wih[(size_t)(n0 + n) * II + (k - HH)];
    }
    if (tid < NPER) bias_s[tid] = bias[n0 + tid];

    // Read barrier generation base before first arrival (safe: no barrier can
    // complete until this CTA arrives).
    unsigned base_gen = *(volatile unsigned*)&g_bar_gen;
    __syncthreads();

    // Zero h0 slice (hidden_states[0] is part of the output).
    for (int i = tid; i < BB * NPER; i += NTHREADS) {
        int b = i >> 3, n = i & 7;
        hstates[(size_t)b * HH + n0 + n] = 0.f;
    }
    unsigned bstep = 1;
    grid_barrier(base_gen, bstep++);

    uint32_t pu[2];
    pu[0] = (uint32_t)__cvta_generic_to_shared(panelA);
    pu[1] = (uint32_t)__cvta_generic_to_shared(panelB);
    float* pf[2] = { panelA, panelB };

    for (int t = 0; t < SS; ++t) {
        const float* hprev = hstates + (size_t)t * (BB * HH);
        float*       hout  = hstates + (size_t)(t + 1) * (BB * HH);

        float acc0[8], acc1[8];
#pragma unroll
        for (int n = 0; n < 8; ++n) { acc0[n] = 0.f; acc1[n] = 0.f; }

        // Panels 0..3: h slices (row stride H); panel 4: x[:, t, :] (row stride S*I).
        stage_panel(hprev, HH, pu[0]);
#pragma unroll 1
        for (int p = 0; p < 5; ++p) {
            if (p < 4) {
                const float* srcB = (p + 1 < 4) ? (hprev + (p + 1) * 256)
                                                : (x + (size_t)t * II);
                int stride = (p + 1 < 4) ? HH : (SS * II);
                stage_panel(srcB, stride, pu[(p + 1) & 1]);
                cp_wait<1>();
            } else {
                cp_wait<0>();
            }
            __syncthreads();
            compute_panel(pf[p & 1], w_s + p * 256, bp, q, acc0, acc1);
            __syncthreads();
        }

        // Cross-q reduction via smem: red[q][b*8+n]
        {
            float* r0 = red + q * 512 + bp * 8;
            *(float4*)(r0)     = make_float4(acc0[0], acc0[1], acc0[2], acc0[3]);
            *(float4*)(r0 + 4) = make_float4(acc0[4], acc0[5], acc0[6], acc0[7]);
            float* r1 = red + q * 512 + (bp + 32) * 8;
            *(float4*)(r1)     = make_float4(acc1[0], acc1[1], acc1[2], acc1[3]);
            *(float4*)(r1 + 4) = make_float4(acc1[4], acc1[5], acc1[6], acc1[7]);
        }
        __syncthreads();
#pragma unroll
        for (int rr = 0; rr < 2; ++rr) {
            int o = tid + rr * NTHREADS;          // 0..511  -> (b, n)
            int b = o >> 3, n = o & 7;
            float s = bias_s[n];
#pragma unroll
            for (int qq = 0; qq < 8; ++qq) s += red[qq * 512 + o];
            hout[(size_t)b * HH + n0 + n] = tanhf(s);
        }
        grid_barrier(base_gen, bstep++);
    }
}

// Final FC: out[b][o] = hlast[b] . fc_w[o] + fc_b[o]
__global__ void __launch_bounds__(NTHREADS)
fc_kernel(const float* __restrict__ hlast,
          const float* __restrict__ fcw,
          const float* __restrict__ fcb,
          float* __restrict__ out)
{
    __shared__ float hrow[HH];
    int b = blockIdx.x;
    for (int i = threadIdx.x; i < HH; i += NTHREADS)
        hrow[i] = hlast[(size_t)b * HH + i];
    __syncthreads();

    int o = threadIdx.x;
    const float* w = fcw + (size_t)o * HH;
    float acc = 0.f;
#pragma unroll 4
    for (int k = 0; k < HH; k += 4) {
        float4 wv = *(const float4*)(w + k);
        acc = fmaf(hrow[k],     wv.x,
              fmaf(hrow[k + 1], wv.y,
              fmaf(hrow[k + 2], wv.z,
              fmaf(hrow[k + 3], wv.w, acc))));
    }
    out[(size_t)b * OO + o] = acc + fcb[o];
}

extern "C" void kernel_launch(void* const* d_in, const int* in_sizes, int n_in,
                              void* d_out, int out_size) {
    const float* x    = (const float*)d_in[0];   // [64,512,256]
    const float* wih  = (const float*)d_in[1];   // [1024,256]
    const float* whh  = (const float*)d_in[2];   // [1024,1024]
    const float* bias = (const float*)d_in[3];   // [1024]
    const float* fcw  = (const float*)d_in[4];   // [256,1024]
    const float* fcb  = (const float*)d_in[5];   // [256]

    float* out     = (float*)d_out;              // output [64,256] first
    float* hstates = out + (size_t)BB * OO;      // then hidden_states [513,64,1024]

    cudaFuncSetAttribute(rnn_persistent_kernel,
                         cudaFuncAttributeMaxDynamicSharedMemorySize, SMEM_BYTES);

    rnn_persistent_kernel<<<NBLOCKS, NTHREADS, SMEM_BYTES>>>(x, wih, whh, bias, hstates);

    const float* hlast = hstates + (size_t)SS * (BB * HH);
    fc_kernel<<<BB, NTHREADS>>>(hlast, fcw, fcb, out);
}

// round 7
// speedup vs baseline: 1.1577x; 1.1577x over previous
#include <cuda_runtime.h>
#include <cstdint>

#define NBLOCKS   128
#define NTHREADS  256
#define BB        64
#define HH        1024
#define II        256
#define SS        512
#define OO        256
#define KTOT      1280
#define NPER      8

typedef unsigned long long ull;

// ---------------- device scratch (no cudaMalloc allowed) ----------------
__device__ float g_xt[SS * II * BB];      // x transposed: [t][k][b]  (33.5 MB)
__device__ float g_hx[2][HH * BB];        // h exchange, transposed: [parity][k][b]

// ---------------- grid barrier ----------------
__device__ unsigned g_bar_count = 0;
__device__ unsigned g_bar_gen   = 0;

__device__ __forceinline__ void grid_barrier(unsigned base_gen, unsigned step) {
    __syncthreads();
    if (threadIdx.x == 0) {
        __threadfence();
        unsigned prev = atomicAdd(&g_bar_count, 1u);
        if (prev == NBLOCKS - 1) {
            g_bar_count = 0;
            __threadfence();
            atomicAdd(&g_bar_gen, 1u);
        } else {
            while (*(volatile unsigned*)&g_bar_gen - base_gen < step) { }
        }
        __threadfence();
    }
    __syncthreads();
}

// ---------------- cp.async ----------------
__device__ __forceinline__ void cp_async16(uint32_t dst, const void* src) {
    asm volatile("cp.async.cg.shared.global [%0], [%1], 16;" :: "r"(dst), "l"(src));
}
__device__ __forceinline__ void cp_commit() {
    asm volatile("cp.async.commit_group;" ::: "memory");
}
template <int N>
__device__ __forceinline__ void cp_wait() {
    asm volatile("cp.async.wait_group %0;" :: "n"(N) : "memory");
}

// ---------------- f32x2 helpers ----------------
#define LDSV2(a, b, addr) \
    asm volatile("ld.shared.v2.u64 {%0,%1},[%2];" : "=l"(a), "=l"(b) : "r"(addr))
#define FMA2(d, x, y) \
    asm volatile("fma.rn.f32x2 %0,%1,%2,%0;" : "+l"(d) : "l"(x), "l"(y))
#define ADD2(d, a, b) \
    asm volatile("add.rn.f32x2 %0,%1,%2;" : "=l"(d) : "l"(a), "l"(b))
#define UNPK(lo, hi, v) \
    asm volatile("mov.b64 {%0,%1},%2;" : "=f"(lo), "=f"(hi) : "l"(v))
#define STSV2(addr, a, b) \
    asm volatile("st.shared.v2.f32 [%0],{%1,%2};" :: "r"(addr), "f"(a), "f"(b) : "memory")

// ---------------- smem layout (bytes) ----------------
//   panels[4]  : 4 * 128*64*4   = 131072
//   w_t        : 1280*8*4       =  40960
//   w_ts       : 1280*8*4       =  40960   (pair-swapped)
//   red        : 8*8*66*4       =  16896
//   bias       : 32
static constexpr int OFF_PAN  = 0;
static constexpr int PAN_BYTES = 128 * 64 * 4;           // 32768
static constexpr int OFF_WT   = 4 * PAN_BYTES;           // 131072
static constexpr int OFF_WTS  = OFF_WT + 40960;          // 172032
static constexpr int OFF_RED  = OFF_WTS + 40960;         // 212992
static constexpr int OFF_BIAS = OFF_RED + 16896;         // 229888
static constexpr int SMEM_BYTES = OFF_BIAS + 64;         // 229952

// Stage one contiguous 32KB panel into smem.
__device__ __forceinline__ void stage32k(const float* __restrict__ src, uint32_t dst) {
#pragma unroll
    for (int j = 0; j < 8; ++j) {
        int idx = threadIdx.x + j * NTHREADS;   // float4 index 0..2047
        cp_async16(dst + (uint32_t)idx * 16u, src + (size_t)idx * 4);
    }
    cp_commit();
}

// One 128-k panel: this thread's 4 k values, 8b x 8n tile, diagonal f32x2 pairing.
__device__ __forceinline__ void compute_panel(uint32_t pan, uint32_t wt, uint32_t wts,
                                              int kb, int bt, int kc, ull acc[32]) {
    uint32_t ha = pan + (uint32_t)(kc * 4) * 256u + (uint32_t)bt * 32u;
    uint32_t wa = wt  + (uint32_t)(kb + kc * 4) * 32u;
    uint32_t sa = wts + (uint32_t)(kb + kc * 4) * 32u;
#pragma unroll
    for (int kk = 0; kk < 4; ++kk) {
        ull h[4], w[4], s[4];
        LDSV2(h[0], h[1], ha);
        LDSV2(h[2], h[3], ha + 16u);
        LDSV2(w[0], w[1], wa);
        LDSV2(w[2], w[3], wa + 16u);
        LDSV2(s[0], s[1], sa);
        LDSV2(s[2], s[3], sa + 16u);
#pragma unroll
        for (int I = 0; I < 4; ++I) {
#pragma unroll
            for (int J = 0; J < 4; ++J) {
                FMA2(acc[I * 4 + J],      h[I], w[J]);   // (2I,2J) , (2I+1,2J+1)
                FMA2(acc[16 + I * 4 + J], h[I], s[J]);   // (2I,2J+1), (2I+1,2J)
            }
        }
        ha += 256u; wa += 32u; sa += 32u;
    }
}

__global__ void __launch_bounds__(NTHREADS, 1)
rnn_persistent_kernel(const float* __restrict__ wih,
                      const float* __restrict__ whh,
                      const float* __restrict__ bias,
                      float* __restrict__ hstates)   // [S+1][B][H]
{
    extern __shared__ float smem_f[];
    const uint32_t sbase = (uint32_t)__cvta_generic_to_shared(smem_f);
    const uint32_t u_wt  = sbase + OFF_WT;
    const uint32_t u_wts = sbase + OFF_WTS;
    float* red_f  = smem_f + OFF_RED / 4;
    float* bias_s = smem_f + OFF_BIAS / 4;

    const int tid  = threadIdx.x;
    const int lane = tid & 31;
    const int warp = tid >> 5;
    const int bt   = lane & 7;               // b-tile: b = bt*8 .. bt*8+7
    const int kc   = warp * 4 + (lane >> 3); // k-chunk 0..31 (4 k per 128-k panel)
    const int n0   = blockIdx.x * NPER;

    // Build combined weight rows [k][8n], normal + pair-swapped.
    for (int i = tid; i < KTOT * NPER; i += NTHREADS) {
        int k = i >> 3, n = i & 7;
        float v = (k < HH) ? whh[(size_t)(n0 + n) * HH + k]
                           : wih[(size_t)(n0 + n) * II + (k - HH)];
        smem_f[OFF_WT / 4 + k * 8 + n]         = v;
        smem_f[OFF_WTS / 4 + k * 8 + (n ^ 1)]  = v;
    }
    if (tid < NPER) bias_s[tid] = bias[n0 + tid];

    unsigned base_gen = *(volatile unsigned*)&g_bar_gen;

    // Prologue: prefetch the two x-panels for t=0 (slots 0, 1).
    stage32k(g_xt + 0, sbase + OFF_PAN + 0 * PAN_BYTES);
    stage32k(g_xt + 8192, sbase + OFF_PAN + 1 * PAN_BYTES);
    __syncthreads();   // w_t/w_ts/bias ready

    unsigned bstep = 1;

#pragma unroll 1
    for (int t = 0; t < SS; ++t) {
        const float* hx_src = g_hx[t & 1];
        ull acc[32];
#pragma unroll
        for (int i = 0; i < 32; ++i) acc[i] = 0ull;

        // Panels: p0,p1 = x (w-k base 1024,1152); p2..p9 = h (w-k base 0..896).
#pragma unroll 1
        for (int p = 0; p < 10; ++p) {
            int next = p + 2;
            uint32_t nslot = sbase + OFF_PAN + (uint32_t)(((2 * t + next) & 3)) * PAN_BYTES;
            if (next < 10) {
                stage32k(hx_src + (size_t)(next - 2) * 8192, nslot);
            } else {
                int tn = (t + 1 < SS) ? (t + 1) : t;
                stage32k(g_xt + (size_t)tn * 16384 + (size_t)(next - 10) * 8192, nslot);
            }
            cp_wait<2>();
            __syncthreads();
            uint32_t cslot = sbase + OFF_PAN + (uint32_t)(((2 * t + p) & 3)) * PAN_BYTES;
            int kb = (p < 2) ? (HH + p * 128) : ((p - 2) * 128);
            compute_panel(cslot, u_wt, u_wts, kb, bt, kc, acc);
        }

        // In-warp reduction over the 4 k-chunk groups (xor 8, 16).
#pragma unroll
        for (int r = 8; r <= 16; r <<= 1) {
#pragma unroll
            for (int i = 0; i < 32; ++i) {
                ull o = __shfl_xor_sync(0xffffffffu, acc[i], r);
                ADD2(acc[i], acc[i], o);
            }
        }

        // Lanes 0-7 write unscrambled partials: red[warp][bt][bi*8+n]  (stride 66)
        if (lane < 8) {
            uint32_t rb = sbase + OFF_RED + (uint32_t)(warp * 528 + bt * 66) * 4u;
#pragma unroll
            for (int I = 0; I < 4; ++I) {
#pragma unroll
                for (int J = 0; J < 4; ++J) {
                    float dlo, dhi, alo, ahi;
                    UNPK(dlo, dhi, acc[I * 4 + J]);
                    UNPK(alo, ahi, acc[16 + I * 4 + J]);
                    STSV2(rb + (uint32_t)((2 * I) * 8 + 2 * J) * 4u, dlo, alo);
                    STSV2(rb + (uint32_t)((2 * I + 1) * 8 + 2 * J) * 4u, ahi, dhi);
                }
            }
        }
        __syncthreads();

        // Final cross-warp sum + bias + tanh; write hstates and transposed g_hx.
        float* hout = hstates + (size_t)(t + 1) * (BB * HH);
        float* hx_dst = g_hx[(t + 1) & 1];
#pragma unroll
        for (int rr = 0; rr < 2; ++rr) {
            int o  = tid + rr * NTHREADS;      // 0..511
            int obt = o >> 6, c = o & 63;
            int bi = c >> 3, n = c & 7;
            float s2 = bias_s[n];
#pragma unroll
            for (int w = 0; w < 8; ++w) s2 += red_f[w * 528 + obt * 66 + c];
            float hval = tanhf(s2);
            int b = obt * 8 + bi;
            hout[(size_t)b * HH + n0 + n] = hval;
            hx_dst[(n0 + n) * BB + b] = hval;
        }

        grid_barrier(base_gen, bstep++);
    }
    cp_wait<0>();
}

// ---------------- x transpose: x[b][t][k] -> g_xt[t][k][b] ----------------
__global__ void transpose_x_kernel(const float* __restrict__ x) {
    __shared__ float tile[32][33];
    int k0 = blockIdx.x * 32, b0 = blockIdx.y * 32, t = blockIdx.z;
    int tx = threadIdx.x, ty = threadIdx.y;
#pragma unroll
    for (int i = 0; i < 4; ++i) {
        int b = b0 + ty + i * 8;
        tile[ty + i * 8][tx] = x[(size_t)b * (SS * II) + (size_t)t * II + k0 + tx];
    }
    __syncthreads();
#pragma unroll
    for (int i = 0; i < 4; ++i) {
        int k = k0 + ty + i * 8;
        g_xt[(size_t)t * (II * BB) + (size_t)k * BB + b0 + tx] = tile[tx][ty + i * 8];
    }
}

// ---------------- init: zero h0 (output slice + exchange buffer) ----------------
__global__ void init_zero_kernel(float* __restrict__ hstates) {
    int i = blockIdx.x * blockDim.x + threadIdx.x;
    if (i < BB * HH) {
        hstates[i] = 0.f;
        g_hx[0][i] = 0.f;
    }
}

// ---------------- final FC ----------------
__global__ void __launch_bounds__(NTHREADS)
fc_kernel(const float* __restrict__ hlast,
          const float* __restrict__ fcw,
          const float* __restrict__ fcb,
          float* __restrict__ out)
{
    __shared__ float hrow[HH];
    int b = blockIdx.x;
    for (int i = threadIdx.x; i < HH; i += NTHREADS)
        hrow[i] = hlast[(size_t)b * HH + i];
    __syncthreads();

    int o = threadIdx.x;
    const float* w = fcw + (size_t)o * HH;
    float acc = 0.f;
#pragma unroll 4
    for (int k = 0; k < HH; k += 4) {
        float4 wv = *(const float4*)(w + k);
        acc = fmaf(hrow[k],     wv.x,
              fmaf(hrow[k + 1], wv.y,
              fmaf(hrow[k + 2], wv.z,
              fmaf(hrow[k + 3], wv.w, acc))));
    }
    out[(size_t)b * OO + o] = acc + fcb[o];
}

extern "C" void kernel_launch(void* const* d_in, const int* in_sizes, int n_in,
                              void* d_out, int out_size) {
    const float* x    = (const float*)d_in[0];   // [64,512,256]
    const float* wih  = (const float*)d_in[1];   // [1024,256]
    const float* whh  = (const float*)d_in[2];   // [1024,1024]
    const float* bias = (const float*)d_in[3];   // [1024]
    const float* fcw  = (const float*)d_in[4];   // [256,1024]
    const float* fcb  = (const float*)d_in[5];   // [256]

    float* out     = (float*)d_out;              // output [64,256] first
    float* hstates = out + (size_t)BB * OO;      // hidden_states [513,64,1024]

    cudaFuncSetAttribute(rnn_persistent_kernel,
                         cudaFuncAttributeMaxDynamicSharedMemorySize, SMEM_BYTES);

    transpose_x_kernel<<<dim3(II / 32, BB / 32, SS), dim3(32, 8)>>>(x);
    init_zero_kernel<<<(BB * HH + 255) / 256, 256>>>(hstates);

    rnn_persistent_kernel<<<NBLOCKS, NTHREADS, SMEM_BYTES>>>(wih, whh, bias, hstates);

    const float* hlast = hstates + (size_t)SS * (BB * HH);
    fc_kernel<<<BB, NTHREADS>>>(hlast, fcw, fcb, out);
}

// round 9
// speedup vs baseline: 1.4480x; 1.2508x over previous
#include <cuda_runtime.h>
#include <cstdint>

#define NBLOCKS   128
#define NTHREADS  256
#define BB        64
#define HH        1024
#define II        256
#define SS        512
#define OO        256
#define KTOT      1280
#define NPER      8

typedef unsigned long long ull;

// ---------------- device scratch ----------------
__device__ float g_xt[SS * II * BB];      // x: [t][kp][b][2]  (k-pair interleaved)
__device__ float g_hx[2][HH * BB];        // h exchange: [parity][kp][b][2]

// ---------------- grid barrier ----------------
__device__ unsigned g_bar_count = 0;
__device__ unsigned g_bar_gen   = 0;

__device__ __forceinline__ void grid_barrier(unsigned base_gen, unsigned step) {
    __syncthreads();
    if (threadIdx.x == 0) {
        __threadfence();
        unsigned prev = atomicAdd(&g_bar_count, 1u);
        if (prev == NBLOCKS - 1) {
            g_bar_count = 0;
            __threadfence();
            atomicAdd(&g_bar_gen, 1u);
        } else {
            while (*(volatile unsigned*)&g_bar_gen - base_gen < step) { }
        }
        __threadfence();
    }
    __syncthreads();
}

// ---------------- cp.async ----------------
__device__ __forceinline__ void cp_async16(uint32_t dst, const void* src) {
    asm volatile("cp.async.cg.shared.global [%0], [%1], 16;" :: "r"(dst), "l"(src));
}
__device__ __forceinline__ void cp_commit() {
    asm volatile("cp.async.commit_group;" ::: "memory");
}
template <int N>
__device__ __forceinline__ void cp_wait() {
    asm volatile("cp.async.wait_group %0;" :: "n"(N) : "memory");
}

// ---------------- f32x2 helpers ----------------
#define LDSV2(a, b, addr) \
    asm volatile("ld.shared.v2.u64 {%0,%1},[%2];" : "=l"(a), "=l"(b) : "r"(addr))
#define FMA2(d, x, y) \
    asm volatile("fma.rn.f32x2 %0,%1,%2,%0;" : "+l"(d) : "l"(x), "l"(y))
#define UNPK(lo, hi, v) \
    asm volatile("mov.b64 {%0,%1},%2;" : "=f"(lo), "=f"(hi) : "l"(v))

// Extended SW128 swizzle: XOR bits[6:4] with bits[9:7] AND bit4 with bit10.
__device__ __forceinline__ uint32_t swx(uint32_t o) {
    return o ^ ((o >> 3) & 0x70u) ^ ((o >> 6) & 0x10u);
}

// ---------------- smem layout (bytes) ----------------
//   panels[4] : 4 * 32768 = 131072   ([kp 0..63][b][2], swizzled)
//   w_t       : 640*16*4  =  40960   ([kp][n][2], swizzled)
//   red       : 8*544*4   =  17408   (stride 68 per bt row: 16B-aligned, bank-tiled)
//   bias      : 64
static constexpr int OFF_PAN  = 0;
static constexpr int PAN_BYTES = 32768;
static constexpr int OFF_WT   = 4 * PAN_BYTES;            // 131072
static constexpr int OFF_RED  = OFF_WT + 40960;           // 172032
static constexpr int OFF_BIAS = OFF_RED + 17408;          // 189440
static constexpr int SMEM_BYTES = OFF_BIAS + 64;          // 189504

// Stage one contiguous 32KB block into a swizzled smem panel.
__device__ __forceinline__ void stage32k(const float* __restrict__ src, uint32_t dst) {
#pragma unroll
    for (int j = 0; j < 8; ++j) {
        int idx = threadIdx.x + j * NTHREADS;           // 16B-chunk 0..2047
        cp_async16(dst + swx((uint32_t)idx * 16u), src + (size_t)idx * 4);
    }
    cp_commit();
}

// One 128-k panel (64 kp rows). Thread covers kp = kc, kc+32; tile 8b x 8n.
__device__ __forceinline__ void compute_panel(uint32_t pan, uint32_t wt,
                                              int kp_base, int bt, int kc,
                                              ull acc[64]) {
#pragma unroll
    for (int kk = 0; kk < 2; ++kk) {
        int kpl = kc + 32 * kk;
        uint32_t hB = (uint32_t)(kpl * 512 + bt * 64);
        uint32_t wB = (uint32_t)((kp_base + kpl) * 64);
        uint32_t hX = ((hB >> 3) & 0x70u) ^ ((hB >> 6) & 0x10u);
        uint32_t wX = ((wB >> 3) & 0x70u) ^ ((wB >> 6) & 0x10u);
        ull h[8], w[8];
#pragma unroll
        for (int i = 0; i < 4; ++i)
            LDSV2(h[2 * i], h[2 * i + 1], pan + ((hB + (uint32_t)i * 16u) ^ hX));
#pragma unroll
        for (int j = 0; j < 4; ++j)
            LDSV2(w[2 * j], w[2 * j + 1], wt + ((wB + (uint32_t)j * 16u) ^ wX));
#pragma unroll
        for (int I = 0; I < 8; ++I)
#pragma unroll
            for (int J = 0; J < 8; ++J)
                FMA2(acc[I * 8 + J], h[I], w[J]);
    }
}

__global__ void __launch_bounds__(NTHREADS, 1)
rnn_persistent_kernel(const float* __restrict__ wih,
                      const float* __restrict__ whh,
                      const float* __restrict__ bias,
                      float* __restrict__ hstates)   // [S+1][B][H]
{
    extern __shared__ float smem_f[];
    const uint32_t sbase = (uint32_t)__cvta_generic_to_shared(smem_f);
    const uint32_t u_wt  = sbase + OFF_WT;
    float* red_f  = smem_f + OFF_RED / 4;
    float* bias_s = smem_f + OFF_BIAS / 4;

    const int tid  = threadIdx.x;
    const int lane = tid & 31;
    const int warp = tid >> 5;
    const int bt   = lane & 7;                // b = bt*8 .. bt*8+7
    const int kc   = warp * 4 + (lane >> 3);  // 0..31
    const int n0   = blockIdx.x * NPER;

    // Fill weights: w(k, n) -> smem [kp][n][2], swizzled.  k<1024: W_hh, else W_ih.
    for (int i = tid; i < KTOT * NPER; i += NTHREADS) {
        int k = i >> 3, n = i & 7;
        float v = (k < HH) ? whh[(size_t)(n0 + n) * HH + k]
                           : wih[(size_t)(n0 + n) * II + (k - HH)];
        uint32_t byteoff = (uint32_t)(((k >> 1) * 16 + n * 2 + (k & 1)) * 4);
        *(float*)((char*)smem_f + OFF_WT + swx(byteoff)) = v;
    }
    if (tid < NPER) bias_s[tid] = bias[n0 + tid];

    unsigned base_gen = *(volatile unsigned*)&g_bar_gen;

    // Prologue: prefetch the two x-panels for t=0 into slots 0, 1.
    stage32k(g_xt + 0,    sbase + OFF_PAN + 0 * PAN_BYTES);
    stage32k(g_xt + 8192, sbase + OFF_PAN + 1 * PAN_BYTES);
    __syncthreads();   // weights/bias ready

    unsigned bstep = 1;

#pragma unroll 1
    for (int t = 0; t < SS; ++t) {
        const float* hx_src = g_hx[t & 1];
        ull acc[64];
#pragma unroll
        for (int i = 0; i < 64; ++i) acc[i] = 0ull;

        // Panels: p0,p1 = x (kp_base 512, 576); p2..p9 = h (kp_base 0..448).
#pragma unroll 1
        for (int p = 0; p < 10; ++p) {
            int next = p + 2;
            uint32_t nslot = sbase + OFF_PAN + (uint32_t)((2 * t + next) & 3) * PAN_BYTES;
            if (next < 10) {
                stage32k(hx_src + (size_t)(next - 2) * 8192, nslot);
            } else {
                int tn = (t + 1 < SS) ? (t + 1) : t;
                stage32k(g_xt + (size_t)tn * 16384 + (size_t)(next - 10) * 8192, nslot);
            }
            cp_wait<2>();
            __syncthreads();
            uint32_t cslot = sbase + OFF_PAN + (uint32_t)((2 * t + p) & 3) * PAN_BYTES;
            int kp_base = (p < 2) ? (512 + p * 64) : ((p - 2) * 64);
            compute_panel(cslot, u_wt, kp_base, bt, kc, acc);
        }

        // Fold k-parity pairs, then in-warp reduction over the 4 kc-sub lanes.
        float v[64];
#pragma unroll
        for (int i = 0; i < 64; ++i) {
            float lo, hi; UNPK(lo, hi, acc[i]);
            v[i] = lo + hi;
        }
#pragma unroll
        for (int r = 8; r <= 16; r <<= 1)
#pragma unroll
            for (int i = 0; i < 64; ++i)
                v[i] += __shfl_xor_sync(0xffffffffu, v[i], r);

        // Lanes 0-7 hold warp partials: red[warp][bt*68 + I*8 + J] (stride 68:
        // 272B rows -> 16B-aligned float4 stores, 8 lanes tile all 32 banks).
        if (lane < 8) {
            float* rb = red_f + warp * 544 + bt * 68;
#pragma unroll
            for (int i = 0; i < 64; i += 4)
                *(float4*)(rb + i) = make_float4(v[i], v[i + 1], v[i + 2], v[i + 3]);
        }
        __syncthreads();

        // Cross-warp sum + bias + tanh; write hstates + paired-transposed g_hx.
        float* hout   = hstates + (size_t)(t + 1) * (BB * HH);
        float* hx_dst = g_hx[(t + 1) & 1];
#pragma unroll
        for (int rr = 0; rr < 2; ++rr) {
            int o = tid + rr * NTHREADS;      // 0..511
            int b = o >> 3, n = o & 7;
            int ri = (b >> 3) * 68 + (b & 7) * 8 + n;
            float s = bias_s[n];
#pragma unroll
            for (int w = 0; w < 8; ++w) s += red_f[w * 544 + ri];
            float hv = tanhf(s);
            hout[(size_t)b * HH + n0 + n] = hv;
            int kg = n0 + n;
            hx_dst[((kg >> 1) * 128) + b * 2 + (kg & 1)] = hv;
        }

        grid_barrier(base_gen, bstep++);
    }
    cp_wait<0>();
}

// ---------------- x transpose: x[b][t][k] -> g_xt[t][kp][b][2] ----------------
__global__ void transpose_x_kernel(const float* __restrict__ x) {
    __shared__ float tile[32][33];
    int k0 = blockIdx.x * 32, b0 = blockIdx.y * 32, t = blockIdx.z;
    int tx = threadIdx.x, ty = threadIdx.y;
#pragma unroll
    for (int i = 0; i < 4; ++i) {
        int b = b0 + ty + i * 8;
        tile[ty + i * 8][tx] = x[(size_t)b * (SS * II) + (size_t)t * II + k0 + tx];
    }
    __syncthreads();
#pragma unroll
    for (int i = 0; i < 4; ++i) {
        int k = k0 + ty + i * 8;
        int b = b0 + tx;
        g_xt[(size_t)t * 16384 + (size_t)(k >> 1) * 128 + b * 2 + (k & 1)] =
            tile[tx][ty + i * 8];
    }
}

// ---------------- init: zero h0 ----------------
__global__ void init_zero_kernel(float* __restrict__ hstates) {
    int i = blockIdx.x * blockDim.x + threadIdx.x;
    if (i < BB * HH) {
        hstates[i] = 0.f;
        g_hx[0][i] = 0.f;
    }
}

// ---------------- final FC ----------------
__global__ void __launch_bounds__(NTHREADS)
fc_kernel(const float* __restrict__ hlast,
          const float* __restrict__ fcw,
          const float* __restrict__ fcb,
          float* __restrict__ out)
{
    __shared__ float hrow[HH];
    int b = blockIdx.x;
    for (int i = threadIdx.x; i < HH; i += NTHREADS)
        hrow[i] = hlast[(size_t)b * HH + i];
    __syncthreads();

    int o = threadIdx.x;
    const float* w = fcw + (size_t)o * HH;
    float acc = 0.f;
#pragma unroll 4
    for (int k = 0; k < HH; k += 4) {
        float4 wv = *(const float4*)(w + k);
        acc = fmaf(hrow[k],     wv.x,
              fmaf(hrow[k + 1], wv.y,
              fmaf(hrow[k + 2], wv.z,
              fmaf(hrow[k + 3], wv.w, acc))));
    }
    out[(size_t)b * OO + o] = acc + fcb[o];
}

extern "C" void kernel_launch(void* const* d_in, const int* in_sizes, int n_in,
                              void* d_out, int out_size) {
    const float* x    = (const float*)d_in[0];   // [64,512,256]
    const float* wih  = (const float*)d_in[1];   // [1024,256]
    const float* whh  = (const float*)d_in[2];   // [1024,1024]
    const float* bias = (const float*)d_in[3];   // [1024]
    const float* fcw  = (const float*)d_in[4];   // [256,1024]
    const float* fcb  = (const float*)d_in[5];   // [256]

    float* out     = (float*)d_out;              // output [64,256]
    float* hstates = out + (size_t)BB * OO;      // hidden_states [513,64,1024]

    cudaFuncSetAttribute(rnn_persistent_kernel,
                         cudaFuncAttributeMaxDynamicSharedMemorySize, SMEM_BYTES);

    transpose_x_kernel<<<dim3(II / 32, BB / 32, SS), dim3(32, 8)>>>(x);
    init_zero_kernel<<<(BB * HH + 255) / 256, 256>>>(hstates);

    rnn_persistent_kernel<<<NBLOCKS, NTHREADS, SMEM_BYTES>>>(wih, whh, bias, hstates);

    const float* hlast = hstates + (size_t)SS * (BB * HH);
    fc_kernel<<<BB, NTHREADS>>>(hlast, fcw, fcb, out);
}